// round 5
// baseline (speedup 1.0000x reference)
#include <cuda_runtime.h>
#include <math.h>

// ---------------- problem constants ----------------
#define H     1900
#define FH    7600      // 4*H
#define KP    1904      // H padded to mult of 16 (K dim)
#define NP1   1920      // H padded to mult of 64 (N of gemm1)
#define NP2   7616      // 4H padded to mult of 64 (N of gemm2)
#define TSTEPS 153
#define TEPI   25
#define NB     256      // batch
#define BBATCH 512      // combined batch (tot rows 0..255, epi rows 256..511)
#define EMB    10
#define PADTOK 26

// ---------------- device scratch (static, no allocs) ----------------
__device__ __align__(16) float g_whn [KP * NP2];   // weight-normed wh, padded [1904][7616]
__device__ __align__(16) float g_wmhn[KP * NP1];   // weight-normed wmh, padded [1904][1920]
__device__ __align__(16) float g_wxn [EMB * NP2];  // [10][7616]
__device__ __align__(16) float g_wmxn[EMB * NP1];  // [10][1920]
__device__ __align__(16) float g_xs  [TSTEPS * BBATCH * EMB]; // embedded inputs per step
__device__ __align__(16) float g_h   [BBATCH * KP];
__device__ __align__(16) float g_c   [BBATCH * KP];
__device__ __align__(16) float g_m   [BBATCH * KP];
__device__ __align__(16) float g_z   [BBATCH * NP2];
__device__ __align__(16) float g_epih[NB * H];
__device__ __align__(16) float g_toth[NB * H];
__device__ int g_ei[NB];
__device__ int g_ti[NB];

// ---------------- weight norm: out = w * g / ||w_col||, into padded layout ----------------
__global__ void wnorm_kernel(const float* __restrict__ w, const float* __restrict__ g, int mode)
{
    float* out; int K, N, KPp, NPp;
    if (mode == 0)      { out = g_whn;  K = H;   N = FH; KPp = KP;  NPp = NP2; }
    else if (mode == 1) { out = g_wmhn; K = H;   N = H;  KPp = KP;  NPp = NP1; }
    else if (mode == 2) { out = g_wxn;  K = EMB; N = FH; KPp = EMB; NPp = NP2; }
    else                { out = g_wmxn; K = EMB; N = H;  KPp = EMB; NPp = NP1; }

    int j = blockIdx.x * blockDim.x + threadIdx.x;
    if (j >= NPp) return;
    if (j >= N) {
        for (int k = 0; k < KPp; k++) out[k * NPp + j] = 0.f;
        return;
    }
    float s = 0.f;
    for (int k = 0; k < K; k++) { float v = w[k * N + j]; s += v * v; }
    float scale = g[j] / sqrtf(fmaxf(s, 1e-12f));
    for (int k = 0; k < K; k++) out[k * NPp + j] = w[k * N + j] * scale;
    for (int k = K; k < KPp; k++) out[k * NPp + j] = 0.f;
}

// ---------------- lengths / extraction indices ----------------
__global__ void lengths_kernel(const int* __restrict__ epi, const int* __restrict__ lft,
                               const int* __restrict__ rgt)
{
    int b = blockIdx.x * blockDim.x + threadIdx.x;
    if (b >= NB) return;
    int el = 0; for (int t = 0; t < TEPI; t++) el += (epi[b * TEPI + t] != PADTOK);
    int ll = 0; for (int t = 0; t < 64;   t++) ll += (lft[b * 64 + t]   != PADTOK);
    int rl = 0; for (int t = 0; t < 64;   t++) rl += (rgt[b * 64 + t]   != PADTOK);
    ll = max(ll, 1); rl = max(rl, 1);
    int tl = el + ll + rl;
    g_ei[b] = min(max(el - 1, 0), TEPI - 1);
    g_ti[b] = min(max(tl - 1, 0), TSTEPS - 1);
}

// ---------------- embed inputs into per-step layout ----------------
__global__ void embed_kernel(const int* __restrict__ epi, const int* __restrict__ tot,
                             const float* __restrict__ embed)
{
    int idx = blockIdx.x * blockDim.x + threadIdx.x;
    const int totN = TSTEPS * NB * EMB;
    const int epiN = TEPI * NB * EMB;
    if (idx < totN) {
        int e = idx % EMB; int r = (idx / EMB) % NB; int t = idx / (EMB * NB);
        int tok = tot[r * TSTEPS + t];
        g_xs[(t * BBATCH + r) * EMB + e] = embed[tok * EMB + e];
    } else if (idx < totN + epiN) {
        int k = idx - totN;
        int e = k % EMB; int r = (k / EMB) % NB; int t = k / (EMB * NB);
        int tok = epi[r * TEPI + t];
        g_xs[(t * BBATCH + (NB + r)) * EMB + e] = embed[tok * EMB + e];
    }
}

// ---------------- init: zero h, c, m (incl. K pads) ----------------
__global__ void init_kernel()
{
    int idx = blockIdx.x * blockDim.x + threadIdx.x;
    if (idx < BBATCH * KP) { g_h[idx] = 0.f; g_c[idx] = 0.f; g_m[idx] = 0.f; }
}

// ---------------- step GEMM: C = A[Mt,KP] * B[KP,N], fused epilogues ----------------
// MODE 1: A=g_h, B=g_wmhn  -> m = (x@wmxn) * (h@wmhn)        (store to g_m, n<H)
// MODE 2: A=g_m, B=g_whn   -> z = (m@whn) + bias + x@wxn      (store to g_z, n<FH)
#define BM 128
#define BN 64
#define BKK 16

template <int MODE>
__global__ __launch_bounds__(256) void gemm_step(int t, const float* __restrict__ bias)
{
    const float* __restrict__ A  = (MODE == 1) ? g_h    : g_m;
    const float* __restrict__ Bm = (MODE == 1) ? g_wmhn : g_whn;
    const int ldb = (MODE == 1) ? NP1 : NP2;

    __shared__ __align__(16) float As[BKK][BM];
    __shared__ __align__(16) float Bs[BKK][BN];

    const int tid  = threadIdx.x;
    const int row0 = blockIdx.y * BM;
    const int col0 = blockIdx.x * BN;

    float acc[8][4];
#pragma unroll
    for (int i = 0; i < 8; i++)
#pragma unroll
        for (int j = 0; j < 4; j++) acc[i][j] = 0.f;

    const int aRow = tid >> 2;            // 0..63
    const int aCol = (tid & 3) << 2;      // 0,4,8,12
    const int bRow = tid >> 4;            // 0..15
    const int bCol = (tid & 15) << 2;     // 0..60
    const int mbase = (tid >> 4) << 3;    // thread M offset (x8)
    const int nbase = (tid & 15) << 2;    // thread N offset (x4)

    for (int k0 = 0; k0 < KP; k0 += BKK) {
        float4 av0 = *reinterpret_cast<const float4*>(&A[(row0 + aRow) * KP + k0 + aCol]);
        float4 av1 = *reinterpret_cast<const float4*>(&A[(row0 + aRow + 64) * KP + k0 + aCol]);
        float4 bv  = *reinterpret_cast<const float4*>(&Bm[(k0 + bRow) * ldb + col0 + bCol]);
        As[aCol + 0][aRow] = av0.x; As[aCol + 1][aRow] = av0.y;
        As[aCol + 2][aRow] = av0.z; As[aCol + 3][aRow] = av0.w;
        As[aCol + 0][aRow + 64] = av1.x; As[aCol + 1][aRow + 64] = av1.y;
        As[aCol + 2][aRow + 64] = av1.z; As[aCol + 3][aRow + 64] = av1.w;
        *reinterpret_cast<float4*>(&Bs[bRow][bCol]) = bv;
        __syncthreads();
#pragma unroll
        for (int k = 0; k < BKK; k++) {
            float4 a0 = *reinterpret_cast<const float4*>(&As[k][mbase]);
            float4 a1 = *reinterpret_cast<const float4*>(&As[k][mbase + 4]);
            float4 b0 = *reinterpret_cast<const float4*>(&Bs[k][nbase]);
            float av[8] = {a0.x, a0.y, a0.z, a0.w, a1.x, a1.y, a1.z, a1.w};
            float bb[4] = {b0.x, b0.y, b0.z, b0.w};
#pragma unroll
            for (int i = 0; i < 8; i++)
#pragma unroll
                for (int j = 0; j < 4; j++) acc[i][j] += av[i] * bb[j];
        }
        __syncthreads();
    }

    // fused epilogue (x-projection has K=10, negligible)
#pragma unroll
    for (int i = 0; i < 8; i++) {
        const int r = row0 + mbase + i;
        const float* xp = &g_xs[(t * BBATCH + r) * EMB];
        float xv[EMB];
#pragma unroll
        for (int e = 0; e < EMB; e++) xv[e] = xp[e];
        if (MODE == 1) {
#pragma unroll
            for (int q = 0; q < 4; q++) {
                const int n = col0 + nbase + q;
                float xm = 0.f;
#pragma unroll
                for (int e = 0; e < EMB; e++) xm += xv[e] * g_wmxn[e * NP1 + n];
                if (n < H) g_m[r * KP + n] = xm * acc[i][q];
            }
        } else {
#pragma unroll
            for (int q = 0; q < 4; q++) {
                const int n = col0 + nbase + q;
                if (n < FH) {
                    float s = acc[i][q] + bias[n];
#pragma unroll
                    for (int e = 0; e < EMB; e++) s += xv[e] * g_wxn[e * NP2 + n];
                    g_z[r * NP2 + n] = s;
                }
            }
        }
    }
}

// ---------------- gates + state update + snapshot ----------------
__device__ __forceinline__ float sigmf(float x) { return 1.f / (1.f + expf(-x)); }

__global__ void gates_kernel(int t, int Mt)
{
    int idx = blockIdx.x * blockDim.x + threadIdx.x;
    if (idx >= Mt * H) return;
    int row = idx / H;
    int j = idx - row * H;
    const float* zr = &g_z[row * NP2];
    float iv = zr[j];
    float fv = zr[H + j];
    float ov = zr[2 * H + j];
    float uv = zr[3 * H + j];
    float c = g_c[row * KP + j];
    c = sigmf(fv) * c + sigmf(iv) * tanhf(uv);
    float h = sigmf(ov) * tanhf(c);
    g_c[row * KP + j] = c;
    g_h[row * KP + j] = h;
    if (row < NB) {
        if (g_ti[row] == t) g_toth[row * H + j] = h;
    } else {
        int b = row - NB;
        if (g_ei[b] == t) g_epih[b * H + j] = h;
    }
}

// ---------------- classifier: concat -> lrelu/bn1 -> W1 -> lrelu/bn2 -> W2 ----------------
__global__ void classifier_kernel(
    const float* __restrict__ bn1g, const float* __restrict__ bn1b,
    const float* __restrict__ bn1m, const float* __restrict__ bn1v,
    const float* __restrict__ W1,  const float* __restrict__ b1,
    const float* __restrict__ bn2g, const float* __restrict__ bn2b,
    const float* __restrict__ bn2m, const float* __restrict__ bn2v,
    const float* __restrict__ W2,  const float* __restrict__ b2,
    float* __restrict__ out)
{
    __shared__ float xsh[2 * H];     // 3800
    __shared__ float ysh[FH / 20];   // 380
    __shared__ float red[256];
    const int b = blockIdx.x;
    const int tid = threadIdx.x;
    const int IC = 2 * H;        // 3800
    const int OC = IC / 10;      // 380

    for (int k = tid; k < IC; k += 256) {
        float v = (k < H) ? g_toth[b * H + k] : g_epih[b * H + (k - H)];
        v = (v >= 0.f) ? v : 0.3f * v;
        v = (v - bn1m[k]) / sqrtf(bn1v[k] + 1e-3f) * bn1g[k] + bn1b[k];
        xsh[k] = v;
    }
    __syncthreads();
    for (int col = tid; col < OC; col += 256) {
        float s = b1[col];
        for (int k = 0; k < IC; k++) s += xsh[k] * W1[k * OC + col];
        s = (s >= 0.f) ? s : 0.3f * s;
        s = (s - bn2m[col]) / sqrtf(bn2v[col] + 1e-3f) * bn2g[col] + bn2b[col];
        ysh[col] = s;
    }
    __syncthreads();
    float acc = 0.f;
    for (int k = tid; k < OC; k += 256) acc += ysh[k] * W2[k];
    red[tid] = acc;
    __syncthreads();
    for (int s = 128; s > 0; s >>= 1) {
        if (tid < s) red[tid] += red[tid + s];
        __syncthreads();
    }
    if (tid == 0) out[b] = red[0] + b2[0];
}

// ---------------- launch ----------------
extern "C" void kernel_launch(void* const* d_in, const int* in_sizes, int n_in,
                              void* d_out, int out_size)
{
    const int*   epi   = (const int*)  d_in[0];
    const int*   lft   = (const int*)  d_in[1];
    const int*   rgt   = (const int*)  d_in[2];
    const int*   tot   = (const int*)  d_in[3];
    const float* embed = (const float*)d_in[4];
    const float* wx    = (const float*)d_in[5];
    const float* wh    = (const float*)d_in[6];
    const float* wmx   = (const float*)d_in[7];
    const float* wmh   = (const float*)d_in[8];
    const float* bb    = (const float*)d_in[9];
    const float* gx    = (const float*)d_in[10];
    const float* gh    = (const float*)d_in[11];
    const float* gmx   = (const float*)d_in[12];
    const float* gmh   = (const float*)d_in[13];
    float* out = (float*)d_out;

    wnorm_kernel<<<(NP2 + 127) / 128, 128>>>(wh,  gh,  0);
    wnorm_kernel<<<(NP1 + 127) / 128, 128>>>(wmh, gmh, 1);
    wnorm_kernel<<<(NP2 + 127) / 128, 128>>>(wx,  gx,  2);
    wnorm_kernel<<<(NP1 + 127) / 128, 128>>>(wmx, gmx, 3);
    lengths_kernel<<<1, 256>>>(epi, lft, rgt);
    const int embN = TSTEPS * NB * EMB + TEPI * NB * EMB;
    embed_kernel<<<(embN + 255) / 256, 256>>>(epi, tot, embed);
    init_kernel<<<(BBATCH * KP + 255) / 256, 256>>>();

    for (int t = 0; t < TSTEPS; t++) {
        const int Mt = (t < TEPI) ? BBATCH : NB;
        dim3 g1(NP1 / BN, Mt / BM);
        gemm_step<1><<<g1, 256>>>(t, nullptr);
        dim3 g2(NP2 / BN, Mt / BM);
        gemm_step<2><<<g2, 256>>>(t, bb);
        gates_kernel<<<(Mt * H + 255) / 256, 256>>>(t, Mt);
    }

    classifier_kernel<<<NB, 256>>>(
        (const float*)d_in[14], (const float*)d_in[15], (const float*)d_in[16], (const float*)d_in[17],
        (const float*)d_in[18], (const float*)d_in[19],
        (const float*)d_in[20], (const float*)d_in[21], (const float*)d_in[22], (const float*)d_in[23],
        (const float*)d_in[24], (const float*)d_in[25], out);
}

// round 6
// speedup vs baseline: 1.0035x; 1.0035x over previous
#include <cuda_runtime.h>
#include <math.h>

// ---------------- problem constants ----------------
#define H     1900
#define FH    7600      // 4*H
#define KP    1904      // H padded to mult of 16 (K dim)
#define NP1   1920      // H padded to mult of 64 (N of gemm1)
#define NP2   7616      // 4H padded to mult of 64 (N of gemm2)
#define TSTEPS 153
#define TEPI   25
#define NB     256      // batch
#define BBATCH 512      // combined batch (tot rows 0..255, epi rows 256..511)
#define EMB    10
#define PADTOK 26

// ---------------- device scratch (static, no allocs) ----------------
__device__ __align__(16) float g_whn [KP * NP2];   // weight-normed wh, padded [1904][7616]
__device__ __align__(16) float g_wmhn[KP * NP1];   // weight-normed wmh, padded [1904][1920]
__device__ __align__(16) float g_wxn [EMB * NP2];  // [10][7616]
__device__ __align__(16) float g_wmxn[EMB * NP1];  // [10][1920]
__device__ __align__(16) float g_xs  [TSTEPS * BBATCH * EMB]; // embedded inputs per step
__device__ __align__(16) float g_h   [BBATCH * KP];
__device__ __align__(16) float g_c   [BBATCH * KP];
__device__ __align__(16) float g_m   [BBATCH * KP];
__device__ __align__(16) float g_z   [BBATCH * NP2];
__device__ __align__(16) float g_epih[NB * H];
__device__ __align__(16) float g_toth[NB * H];
__device__ int g_ei[NB];
__device__ int g_ti[NB];

// ---------------- weight norm: out = w * g / ||w_col||, into padded layout ----------------
__global__ void wnorm_kernel(const float* __restrict__ w, const float* __restrict__ g, int mode)
{
    float* out; int K, N, KPp, NPp;
    if (mode == 0)      { out = g_whn;  K = H;   N = FH; KPp = KP;  NPp = NP2; }
    else if (mode == 1) { out = g_wmhn; K = H;   N = H;  KPp = KP;  NPp = NP1; }
    else if (mode == 2) { out = g_wxn;  K = EMB; N = FH; KPp = EMB; NPp = NP2; }
    else                { out = g_wmxn; K = EMB; N = H;  KPp = EMB; NPp = NP1; }

    int j = blockIdx.x * blockDim.x + threadIdx.x;
    if (j >= NPp) return;
    if (j >= N) {
        for (int k = 0; k < KPp; k++) out[k * NPp + j] = 0.f;
        return;
    }
    float s = 0.f;
    for (int k = 0; k < K; k++) { float v = w[k * N + j]; s += v * v; }
    float scale = g[j] / sqrtf(fmaxf(s, 1e-12f));
    for (int k = 0; k < K; k++) out[k * NPp + j] = w[k * N + j] * scale;
    for (int k = K; k < KPp; k++) out[k * NPp + j] = 0.f;
}

// ---------------- lengths / extraction indices ----------------
__global__ void lengths_kernel(const int* __restrict__ epi, const int* __restrict__ lft,
                               const int* __restrict__ rgt)
{
    int b = blockIdx.x * blockDim.x + threadIdx.x;
    if (b >= NB) return;
    int el = 0; for (int t = 0; t < TEPI; t++) el += (epi[b * TEPI + t] != PADTOK);
    int ll = 0; for (int t = 0; t < 64;   t++) ll += (lft[b * 64 + t]   != PADTOK);
    int rl = 0; for (int t = 0; t < 64;   t++) rl += (rgt[b * 64 + t]   != PADTOK);
    ll = max(ll, 1); rl = max(rl, 1);
    int tl = el + ll + rl;
    g_ei[b] = min(max(el - 1, 0), TEPI - 1);
    g_ti[b] = min(max(tl - 1, 0), TSTEPS - 1);
}

// ---------------- embed inputs into per-step layout ----------------
__global__ void embed_kernel(const int* __restrict__ epi, const int* __restrict__ tot,
                             const float* __restrict__ embed)
{
    int idx = blockIdx.x * blockDim.x + threadIdx.x;
    const int totN = TSTEPS * NB * EMB;
    const int epiN = TEPI * NB * EMB;
    if (idx < totN) {
        int e = idx % EMB; int r = (idx / EMB) % NB; int t = idx / (EMB * NB);
        int tok = tot[r * TSTEPS + t];
        g_xs[(t * BBATCH + r) * EMB + e] = embed[tok * EMB + e];
    } else if (idx < totN + epiN) {
        int k = idx - totN;
        int e = k % EMB; int r = (k / EMB) % NB; int t = k / (EMB * NB);
        int tok = epi[r * TEPI + t];
        g_xs[(t * BBATCH + (NB + r)) * EMB + e] = embed[tok * EMB + e];
    }
}

// ---------------- init: zero h, c, m (incl. K pads) ----------------
__global__ void init_kernel()
{
    int idx = blockIdx.x * blockDim.x + threadIdx.x;
    if (idx < BBATCH * KP) { g_h[idx] = 0.f; g_c[idx] = 0.f; g_m[idx] = 0.f; }
}

// ---------------- step GEMM: C = A[Mt,KP] * B[KP,N], fused epilogues ----------------
// MODE 1: A=g_h, B=g_wmhn  -> m = (x@wmxn) * (h@wmhn)        (store to g_m, n<H)
// MODE 2: A=g_m, B=g_whn   -> z = (m@whn) + bias + x@wxn      (store to g_z, n<FH)
#define BM 128
#define BN 64
#define BKK 16

template <int MODE>
__global__ __launch_bounds__(256) void gemm_step(int t, const float* __restrict__ bias)
{
    const float* __restrict__ A  = (MODE == 1) ? g_h    : g_m;
    const float* __restrict__ Bm = (MODE == 1) ? g_wmhn : g_whn;
    const int ldb = (MODE == 1) ? NP1 : NP2;

    __shared__ __align__(16) float As[BKK][BM];
    __shared__ __align__(16) float Bs[BKK][BN];

    const int tid  = threadIdx.x;
    const int row0 = blockIdx.y * BM;
    const int col0 = blockIdx.x * BN;

    float acc[8][4];
#pragma unroll
    for (int i = 0; i < 8; i++)
#pragma unroll
        for (int j = 0; j < 4; j++) acc[i][j] = 0.f;

    const int aRow = tid >> 2;            // 0..63
    const int aCol = (tid & 3) << 2;      // 0,4,8,12
    const int bRow = tid >> 4;            // 0..15
    const int bCol = (tid & 15) << 2;     // 0..60
    const int mbase = (tid >> 4) << 3;    // thread M offset (x8)
    const int nbase = (tid & 15) << 2;    // thread N offset (x4)

    for (int k0 = 0; k0 < KP; k0 += BKK) {
        float4 av0 = *reinterpret_cast<const float4*>(&A[(row0 + aRow) * KP + k0 + aCol]);
        float4 av1 = *reinterpret_cast<const float4*>(&A[(row0 + aRow + 64) * KP + k0 + aCol]);
        float4 bv  = *reinterpret_cast<const float4*>(&Bm[(k0 + bRow) * ldb + col0 + bCol]);
        As[aCol + 0][aRow] = av0.x; As[aCol + 1][aRow] = av0.y;
        As[aCol + 2][aRow] = av0.z; As[aCol + 3][aRow] = av0.w;
        As[aCol + 0][aRow + 64] = av1.x; As[aCol + 1][aRow + 64] = av1.y;
        As[aCol + 2][aRow + 64] = av1.z; As[aCol + 3][aRow + 64] = av1.w;
        *reinterpret_cast<float4*>(&Bs[bRow][bCol]) = bv;
        __syncthreads();
#pragma unroll
        for (int k = 0; k < BKK; k++) {
            float4 a0 = *reinterpret_cast<const float4*>(&As[k][mbase]);
            float4 a1 = *reinterpret_cast<const float4*>(&As[k][mbase + 4]);
            float4 b0 = *reinterpret_cast<const float4*>(&Bs[k][nbase]);
            float av[8] = {a0.x, a0.y, a0.z, a0.w, a1.x, a1.y, a1.z, a1.w};
            float bb[4] = {b0.x, b0.y, b0.z, b0.w};
#pragma unroll
            for (int i = 0; i < 8; i++)
#pragma unroll
                for (int j = 0; j < 4; j++) acc[i][j] += av[i] * bb[j];
        }
        __syncthreads();
    }

    // fused epilogue (x-projection has K=10, negligible)
#pragma unroll
    for (int i = 0; i < 8; i++) {
        const int r = row0 + mbase + i;
        const float* xp = &g_xs[(t * BBATCH + r) * EMB];
        float xv[EMB];
#pragma unroll
        for (int e = 0; e < EMB; e++) xv[e] = xp[e];
        if (MODE == 1) {
#pragma unroll
            for (int q = 0; q < 4; q++) {
                const int n = col0 + nbase + q;
                float xm = 0.f;
#pragma unroll
                for (int e = 0; e < EMB; e++) xm += xv[e] * g_wmxn[e * NP1 + n];
                if (n < H) g_m[r * KP + n] = xm * acc[i][q];
            }
        } else {
#pragma unroll
            for (int q = 0; q < 4; q++) {
                const int n = col0 + nbase + q;
                if (n < FH) {
                    float s = acc[i][q] + bias[n];
#pragma unroll
                    for (int e = 0; e < EMB; e++) s += xv[e] * g_wxn[e * NP2 + n];
                    g_z[r * NP2 + n] = s;
                }
            }
        }
    }
}

// ---------------- gates + state update + snapshot ----------------
__device__ __forceinline__ float sigmf(float x) { return 1.f / (1.f + expf(-x)); }

__global__ void gates_kernel(int t, int Mt)
{
    int idx = blockIdx.x * blockDim.x + threadIdx.x;
    if (idx >= Mt * H) return;
    int row = idx / H;
    int j = idx - row * H;
    const float* zr = &g_z[row * NP2];
    float iv = zr[j];
    float fv = zr[H + j];
    float ov = zr[2 * H + j];
    float uv = zr[3 * H + j];
    float c = g_c[row * KP + j];
    c = sigmf(fv) * c + sigmf(iv) * tanhf(uv);
    float h = sigmf(ov) * tanhf(c);
    g_c[row * KP + j] = c;
    g_h[row * KP + j] = h;
    if (row < NB) {
        if (g_ti[row] == t) g_toth[row * H + j] = h;
    } else {
        int b = row - NB;
        if (g_ei[b] == t) g_epih[b * H + j] = h;
    }
}

// ---------------- classifier: concat -> lrelu/bn1 -> W1 -> lrelu/bn2 -> W2 ----------------
__global__ void classifier_kernel(
    const float* __restrict__ bn1g, const float* __restrict__ bn1b,
    const float* __restrict__ bn1m, const float* __restrict__ bn1v,
    const float* __restrict__ W1,  const float* __restrict__ b1,
    const float* __restrict__ bn2g, const float* __restrict__ bn2b,
    const float* __restrict__ bn2m, const float* __restrict__ bn2v,
    const float* __restrict__ W2,  const float* __restrict__ b2,
    float* __restrict__ out)
{
    __shared__ float xsh[2 * H];     // 3800
    __shared__ float ysh[FH / 20];   // 380
    __shared__ float red[256];
    const int b = blockIdx.x;
    const int tid = threadIdx.x;
    const int IC = 2 * H;        // 3800
    const int OC = IC / 10;      // 380

    for (int k = tid; k < IC; k += 256) {
        float v = (k < H) ? g_toth[b * H + k] : g_epih[b * H + (k - H)];
        v = (v >= 0.f) ? v : 0.3f * v;
        v = (v - bn1m[k]) / sqrtf(bn1v[k] + 1e-3f) * bn1g[k] + bn1b[k];
        xsh[k] = v;
    }
    __syncthreads();
    for (int col = tid; col < OC; col += 256) {
        float s = b1[col];
        for (int k = 0; k < IC; k++) s += xsh[k] * W1[k * OC + col];
        s = (s >= 0.f) ? s : 0.3f * s;
        s = (s - bn2m[col]) / sqrtf(bn2v[col] + 1e-3f) * bn2g[col] + bn2b[col];
        ysh[col] = s;
    }
    __syncthreads();
    float acc = 0.f;
    for (int k = tid; k < OC; k += 256) acc += ysh[k] * W2[k];
    red[tid] = acc;
    __syncthreads();
    for (int s = 128; s > 0; s >>= 1) {
        if (tid < s) red[tid] += red[tid + s];
        __syncthreads();
    }
    if (tid == 0) out[b] = red[0] + b2[0];
}

// ---------------- launch ----------------
extern "C" void kernel_launch(void* const* d_in, const int* in_sizes, int n_in,
                              void* d_out, int out_size)
{
    const int*   epi   = (const int*)  d_in[0];
    const int*   lft   = (const int*)  d_in[1];
    const int*   rgt   = (const int*)  d_in[2];
    const int*   tot   = (const int*)  d_in[3];
    const float* embed = (const float*)d_in[4];
    const float* wx    = (const float*)d_in[5];
    const float* wh    = (const float*)d_in[6];
    const float* wmx   = (const float*)d_in[7];
    const float* wmh   = (const float*)d_in[8];
    const float* bb    = (const float*)d_in[9];
    const float* gx    = (const float*)d_in[10];
    const float* gh    = (const float*)d_in[11];
    const float* gmx   = (const float*)d_in[12];
    const float* gmh   = (const float*)d_in[13];
    float* out = (float*)d_out;

    wnorm_kernel<<<(NP2 + 127) / 128, 128>>>(wh,  gh,  0);
    wnorm_kernel<<<(NP1 + 127) / 128, 128>>>(wmh, gmh, 1);
    wnorm_kernel<<<(NP2 + 127) / 128, 128>>>(wx,  gx,  2);
    wnorm_kernel<<<(NP1 + 127) / 128, 128>>>(wmx, gmx, 3);
    lengths_kernel<<<1, 256>>>(epi, lft, rgt);
    const int embN = TSTEPS * NB * EMB + TEPI * NB * EMB;
    embed_kernel<<<(embN + 255) / 256, 256>>>(epi, tot, embed);
    init_kernel<<<(BBATCH * KP + 255) / 256, 256>>>();

    for (int t = 0; t < TSTEPS; t++) {
        const int Mt = (t < TEPI) ? BBATCH : NB;
        dim3 g1(NP1 / BN, Mt / BM);
        gemm_step<1><<<g1, 256>>>(t, nullptr);
        dim3 g2(NP2 / BN, Mt / BM);
        gemm_step<2><<<g2, 256>>>(t, bb);
        gates_kernel<<<(Mt * H + 255) / 256, 256>>>(t, Mt);
    }

    classifier_kernel<<<NB, 256>>>(
        (const float*)d_in[14], (const float*)d_in[15], (const float*)d_in[16], (const float*)d_in[17],
        (const float*)d_in[18], (const float*)d_in[19],
        (const float*)d_in[20], (const float*)d_in[21], (const float*)d_in[22], (const float*)d_in[23],
        (const float*)d_in[24], (const float*)d_in[25], out);
}

// round 9
// speedup vs baseline: 2.8288x; 2.8189x over previous
#include <cuda_runtime.h>
#include <cuda_bf16.h>
#include <math.h>

typedef unsigned int u32;
typedef unsigned long long u64;

#define H      1900
#define NB     256
#define BB     512
#define TST    153
#define TEPI   25
#define PADTOK 26
#define LDK    3840      // extended K stride: hi(1920) | lo(1920)
#define NP1    1920
#define NP2    7680
#define CHUNKS 90        // 3 passes x 30 chunks of K=64

// ---------------- device scratch ----------------
__device__ __align__(16) __nv_bfloat16 g_whT [(size_t)NP2 * LDK]; // [n][k hi|lo]
__device__ __align__(16) __nv_bfloat16 g_wmhT[(size_t)NP1 * LDK];
__device__ __align__(16) __nv_bfloat16 g_hext[(size_t)BB * LDK];
__device__ __align__(16) __nv_bfloat16 g_mext[(size_t)BB * LDK];
__device__ __align__(16) float g_c[BB * NP1];
__device__ __align__(16) float g_z[(size_t)BB * NP2];
__device__ __align__(16) float g_wxn [10 * NP2];
__device__ __align__(16) float g_wmxp[10 * NP1];
__device__ __align__(16) float g_xs[(size_t)TST * BB * 10];
__device__ __align__(16) float g_toth[NB * H];
__device__ __align__(16) float g_epih[NB * H];
__device__ int g_ei[NB];
__device__ int g_ti[NB];

// ---------------- helpers ----------------
__device__ __forceinline__ u32 smem_u32(const void* p) {
    u32 a;
    asm("{ .reg .u64 t; cvta.to.shared.u64 t, %1; cvt.u32.u64 %0, t; }" : "=r"(a) : "l"(p));
    return a;
}
#define SWZ128(o) ((u32)(o) ^ ((((u32)(o)) >> 3) & 0x70u))

__device__ __forceinline__ void cp16(u32 dst, const void* src) {
    asm volatile("cp.async.cg.shared.global [%0], [%1], 16;" :: "r"(dst), "l"(src) : "memory");
}

// ---------------- prep kernels ----------------
__global__ void wnormT_kernel(const float* __restrict__ w, const float* __restrict__ g, int mode)
{
    // mode 0: wh [1900,7600] -> g_whT ; mode 1: wmh [1900,1900] -> g_wmhT
    int n = blockIdx.x * blockDim.x + threadIdx.x;
    const int N  = mode ? 1900 : 7600;
    const int NP = mode ? NP1 : NP2;
    if (n >= NP) return;
    __nv_bfloat16* out = (mode ? g_wmhT : g_whT) + (size_t)n * LDK;
    if (n >= N) { u32* o = (u32*)out; for (int i = 0; i < LDK / 2; i++) o[i] = 0u; return; }
    float s = 0.f;
    for (int k = 0; k < 1900; k++) { float v = w[(size_t)k * N + n]; s += v * v; }
    float sc = g[n] * rsqrtf(fmaxf(s, 1e-12f));
    for (int k0 = 0; k0 < NP1; k0 += 8) {
        union { __nv_bfloat16 b[8]; uint4 v; } Hi, Lo;
#pragma unroll
        for (int e = 0; e < 8; e++) {
            int k = k0 + e;
            float v = (k < 1900) ? w[(size_t)k * N + n] * sc : 0.f;
            __nv_bfloat16 hb = __float2bfloat16(v);
            Hi.b[e] = hb;
            Lo.b[e] = __float2bfloat16(v - __bfloat162float(hb));
        }
        *(uint4*)(out + k0)       = Hi.v;
        *(uint4*)(out + NP1 + k0) = Lo.v;
    }
}

__global__ void wnormX_kernel(const float* __restrict__ w, const float* __restrict__ g, int mode)
{
    // mode 0: wx [10,7600] -> g_wxn ; mode 1: wmx [10,1900] -> g_wmxp
    int n = blockIdx.x * blockDim.x + threadIdx.x;
    const int N  = mode ? 1900 : 7600;
    const int NP = mode ? NP1 : NP2;
    float* out = mode ? g_wmxp : g_wxn;
    if (n >= NP) return;
    if (n >= N) { for (int k = 0; k < 10; k++) out[k * NP + n] = 0.f; return; }
    float s = 0.f;
    for (int k = 0; k < 10; k++) { float v = w[k * N + n]; s += v * v; }
    float sc = g[n] * rsqrtf(fmaxf(s, 1e-12f));
    for (int k = 0; k < 10; k++) out[k * NP + n] = w[k * N + n] * sc;
}

__global__ void lengths_kernel(const int* __restrict__ epi, const int* __restrict__ lft,
                               const int* __restrict__ rgt)
{
    int b = blockIdx.x * blockDim.x + threadIdx.x;
    if (b >= NB) return;
    int el = 0; for (int t = 0; t < TEPI; t++) el += (epi[b * TEPI + t] != PADTOK);
    int ll = 0; for (int t = 0; t < 64;   t++) ll += (lft[b * 64 + t]   != PADTOK);
    int rl = 0; for (int t = 0; t < 64;   t++) rl += (rgt[b * 64 + t]   != PADTOK);
    ll = max(ll, 1); rl = max(rl, 1);
    int tl = el + ll + rl;
    g_ei[b] = min(max(el - 1, 0), TEPI - 1);
    g_ti[b] = min(max(tl - 1, 0), TST - 1);
}

__global__ void embed_kernel(const int* __restrict__ epi, const int* __restrict__ tot,
                             const float* __restrict__ embed)
{
    int idx = blockIdx.x * blockDim.x + threadIdx.x;
    const int totN = TST * NB * 10;
    const int epiN = TEPI * NB * 10;
    if (idx < totN) {
        int e = idx % 10; int r = (idx / 10) % NB; int t = idx / (10 * NB);
        g_xs[((size_t)t * BB + r) * 10 + e] = embed[tot[r * TST + t] * 10 + e];
    } else if (idx < totN + epiN) {
        int k = idx - totN;
        int e = k % 10; int r = (k / 10) % NB; int t = k / (10 * NB);
        g_xs[((size_t)t * BB + NB + r) * 10 + e] = embed[epi[r * TEPI + t] * 10 + e];
    }
}

__global__ void init_kernel()
{
    int i = blockIdx.x * blockDim.x + threadIdx.x;
    if (i < BB * NP1) { ((u32*)g_hext)[i] = 0u; ((u32*)g_mext)[i] = 0u; g_c[i] = 0.f; }
}

// ---------------- warp-tiled HMMA step GEMM (mma.sync bf16, fp32 accum) ----------------
// MODE 1: m = (x@wmx) .* (h@wmh)   A=g_hext, W=g_wmhT, out g_mext (bf16 hi/lo)
// MODE 2: z = m@wh + b + x@wx      A=g_mext, W=g_whT,  out g_z (f32)
template<int MODE, int TM, int TN>
__global__ void __launch_bounds__(256) mma_gemm(int t, const float* __restrict__ bias)
{
    constexpr int STG   = (TM + TN) * 128;   // bytes per stage
    constexpr int MFRAG = TM / 32;           // m16 frags per warp (warps 2xM)
    constexpr int NFRAG = TN / 32;           // n8 frags per warp  (warps 4xN)
    extern __shared__ char smraw[];
    char* tiles = (char*)((((u64)smraw) + 1023) & ~(u64)1023);
    const u32 tb0 = smem_u32(tiles);
    const int tid = threadIdx.x, lane = tid & 31, wid = tid >> 5;
    const int wm0 = (wid >> 2) * (TM / 2);
    const int wn0 = (wid & 3) * (TN / 4);
    const int row0 = blockIdx.y * TM, col0 = blockIdx.x * TN;
    const __nv_bfloat16* __restrict__ Ap = (MODE == 1) ? g_hext : g_mext;
    const __nv_bfloat16* __restrict__ Wp = (MODE == 1) ? g_wmhT : g_whT;

    float d[MFRAG][NFRAG][4] = {};

    auto load_chunk = [&](int c, int s) {
        int p = c / 30, kc = c - p * 30;
        int ak = ((p == 1) ? NP1 : 0) + kc * 64;
        int bk = ((p == 2) ? NP1 : 0) + kc * 64;
        u32 tb = tb0 + s * STG;
#pragma unroll
        for (int i = 0; i < TM / 32; i++) {
            int seg = tid + i * 256; int r = seg >> 3; int o = (seg & 7) * 16;
            cp16(tb + SWZ128(r * 128 + o),
                 (const char*)(Ap + (size_t)(row0 + r) * LDK + ak) + o);
        }
#pragma unroll
        for (int i = 0; i < TN / 32; i++) {
            int seg = tid + i * 256; int r = seg >> 3; int o = (seg & 7) * 16;
            cp16(tb + TM * 128 + SWZ128(r * 128 + o),
                 (const char*)(Wp + (size_t)(col0 + r) * LDK + bk) + o);
        }
        asm volatile("cp.async.commit_group;" ::: "memory");
    };

    load_chunk(0, 0); load_chunk(1, 1);

    for (int c = 0; c < CHUNKS; c++) {
        int s = c & 1;
        if (c + 1 < CHUNKS) asm volatile("cp.async.wait_group 1;" ::: "memory");
        else                asm volatile("cp.async.wait_group 0;" ::: "memory");
        __syncthreads();
        const u32 As = tb0 + s * STG, Bs = As + TM * 128;
#pragma unroll
        for (int k16 = 0; k16 < 4; k16++) {
            u32 a[MFRAG][4], b[NFRAG][2];
#pragma unroll
            for (int mi = 0; mi < MFRAG; mi++) {
                int r = wm0 + mi * 16 + (lane & 15);
                int cb = k16 * 32 + (lane >> 4) * 16;
                u32 ad = As + r * 128 + (cb ^ ((r & 7) << 4));
                asm volatile("ldmatrix.sync.aligned.m8n8.x4.shared.b16 {%0,%1,%2,%3}, [%4];"
                    : "=r"(a[mi][0]), "=r"(a[mi][1]), "=r"(a[mi][2]), "=r"(a[mi][3]) : "r"(ad));
            }
#pragma unroll
            for (int nb = 0; nb < NFRAG / 2; nb++) {
                int l = lane & 7, q = lane >> 3;
                int r = wn0 + nb * 16 + (q >> 1) * 8 + l;
                int cb = k16 * 32 + (q & 1) * 16;
                u32 ad = Bs + r * 128 + (cb ^ ((r & 7) << 4));
                u32 r0, r1, r2, r3;
                asm volatile("ldmatrix.sync.aligned.m8n8.x4.shared.b16 {%0,%1,%2,%3}, [%4];"
                    : "=r"(r0), "=r"(r1), "=r"(r2), "=r"(r3) : "r"(ad));
                b[nb * 2][0] = r0; b[nb * 2][1] = r1;
                b[nb * 2 + 1][0] = r2; b[nb * 2 + 1][1] = r3;
            }
#pragma unroll
            for (int mi = 0; mi < MFRAG; mi++)
#pragma unroll
                for (int ni = 0; ni < NFRAG; ni++)
                    asm volatile("mma.sync.aligned.m16n8k16.row.col.f32.bf16.bf16.f32 "
                        "{%0,%1,%2,%3}, {%4,%5,%6,%7}, {%8,%9}, {%0,%1,%2,%3};"
                        : "+f"(d[mi][ni][0]), "+f"(d[mi][ni][1]),
                          "+f"(d[mi][ni][2]), "+f"(d[mi][ni][3])
                        : "r"(a[mi][0]), "r"(a[mi][1]), "r"(a[mi][2]), "r"(a[mi][3]),
                          "r"(b[ni][0]), "r"(b[ni][1]));
        }
        __syncthreads();
        if (c + 2 < CHUNKS) load_chunk(c + 2, s);
    }

    // ---- epilogue: fuse rank-10 x-projection via smem ----
    __syncthreads();
    float* xsh = (float*)tiles;          // [TM][10]
    float* wsh = xsh + TM * 10;          // [10][TN]
    float* bsh = wsh + 10 * TN;          // [TN] (MODE 2)
    const float* Wx = (MODE == 1) ? g_wmxp : g_wxn;
    const int NPx = (MODE == 1) ? NP1 : NP2;
    for (int i = tid; i < TM * 10; i += 256)
        xsh[i] = g_xs[((size_t)t * BB + row0 + i / 10) * 10 + (i % 10)];
    for (int i = tid; i < 10 * TN; i += 256)
        wsh[i] = Wx[(i / TN) * NPx + col0 + (i % TN)];
    if (MODE == 2)
        for (int i = tid; i < TN; i += 256) { int n = col0 + i; bsh[i] = (n < 4 * H) ? bias[n] : 0.f; }
    __syncthreads();

#pragma unroll
    for (int mi = 0; mi < MFRAG; mi++)
#pragma unroll
        for (int rh = 0; rh < 2; rh++) {
            int rl = wm0 + mi * 16 + (lane >> 2) + rh * 8;
            int r = row0 + rl;
            float xv[10];
#pragma unroll
            for (int e = 0; e < 10; e++) xv[e] = xsh[rl * 10 + e];
#pragma unroll
            for (int ni = 0; ni < NFRAG; ni++)
#pragma unroll
                for (int c2 = 0; c2 < 2; c2++) {
                    int nl = wn0 + ni * 8 + (lane & 3) * 2 + c2;
                    int n = col0 + nl;
                    float acc = d[mi][ni][rh * 2 + c2];
                    float xp = 0.f;
#pragma unroll
                    for (int e = 0; e < 10; e++) xp += xv[e] * wsh[e * TN + nl];
                    if (MODE == 1) {
                        if (n < H) {
                            float mv = xp * acc;
                            __nv_bfloat16 hb = __float2bfloat16(mv);
                            g_mext[(size_t)r * LDK + n] = hb;
                            g_mext[(size_t)r * LDK + NP1 + n] =
                                __float2bfloat16(mv - __bfloat162float(hb));
                        }
                    } else {
                        if (n < 4 * H) g_z[(size_t)r * NP2 + n] = acc + bsh[nl] + xp;
                    }
                }
        }
}

// ---------------- gates + state update + snapshot ----------------
__device__ __forceinline__ float sigmf(float x) { return 1.f / (1.f + expf(-x)); }

__global__ void gates_kernel(int t, int Mt)
{
    int idx = blockIdx.x * blockDim.x + threadIdx.x;
    if (idx >= Mt * H) return;
    int row = idx / H, j = idx - row * H;
    const float* zr = &g_z[(size_t)row * NP2];
    float iv = zr[j], fv = zr[H + j], ov = zr[2 * H + j], uv = zr[3 * H + j];
    float c = g_c[row * NP1 + j];
    c = sigmf(fv) * c + sigmf(iv) * tanhf(uv);
    float h = sigmf(ov) * tanhf(c);
    g_c[row * NP1 + j] = c;
    __nv_bfloat16 hb = __float2bfloat16(h);
    g_hext[(size_t)row * LDK + j] = hb;
    g_hext[(size_t)row * LDK + NP1 + j] = __float2bfloat16(h - __bfloat162float(hb));
    if (row < NB) { if (g_ti[row] == t) g_toth[row * H + j] = h; }
    else { int b = row - NB; if (g_ei[b] == t) g_epih[b * H + j] = h; }
}

// ---------------- classifier ----------------
__global__ void classifier_kernel(
    const float* __restrict__ bn1g, const float* __restrict__ bn1b,
    const float* __restrict__ bn1m, const float* __restrict__ bn1v,
    const float* __restrict__ W1,  const float* __restrict__ b1,
    const float* __restrict__ bn2g, const float* __restrict__ bn2b,
    const float* __restrict__ bn2m, const float* __restrict__ bn2v,
    const float* __restrict__ W2,  const float* __restrict__ b2,
    float* __restrict__ out)
{
    __shared__ float xsh[2 * H];
    __shared__ float ysh[380];
    __shared__ float red[256];
    const int b = blockIdx.x, tid = threadIdx.x;
    const int IC = 2 * H, OC = 380;
    for (int k = tid; k < IC; k += 256) {
        float v = (k < H) ? g_toth[b * H + k] : g_epih[b * H + (k - H)];
        v = (v >= 0.f) ? v : 0.3f * v;
        v = (v - bn1m[k]) / sqrtf(bn1v[k] + 1e-3f) * bn1g[k] + bn1b[k];
        xsh[k] = v;
    }
    __syncthreads();
    for (int col = tid; col < OC; col += 256) {
        float s = b1[col];
        for (int k = 0; k < IC; k++) s += xsh[k] * W1[k * OC + col];
        s = (s >= 0.f) ? s : 0.3f * s;
        s = (s - bn2m[col]) / sqrtf(bn2v[col] + 1e-3f) * bn2g[col] + bn2b[col];
        ysh[col] = s;
    }
    __syncthreads();
    float acc = 0.f;
    for (int k = tid; k < OC; k += 256) acc += ysh[k] * W2[k];
    red[tid] = acc;
    __syncthreads();
    for (int s = 128; s > 0; s >>= 1) { if (tid < s) red[tid] += red[tid + s]; __syncthreads(); }
    if (tid == 0) out[b] = red[0] + b2[0];
}

// ---------------- launch ----------------
extern "C" void kernel_launch(void* const* d_in, const int* in_sizes, int n_in,
                              void* d_out, int out_size)
{
    const int*   epi   = (const int*)  d_in[0];
    const int*   lft   = (const int*)  d_in[1];
    const int*   rgt   = (const int*)  d_in[2];
    const int*   tot   = (const int*)  d_in[3];
    const float* embed = (const float*)d_in[4];
    const float* wx    = (const float*)d_in[5];
    const float* wh    = (const float*)d_in[6];
    const float* wmx   = (const float*)d_in[7];
    const float* wmh   = (const float*)d_in[8];
    const float* bb    = (const float*)d_in[9];
    const float* gx    = (const float*)d_in[10];
    const float* gh    = (const float*)d_in[11];
    const float* gmx   = (const float*)d_in[12];
    const float* gmh   = (const float*)d_in[13];
    float* out = (float*)d_out;

    const int SM1 = 1024 + 2 * (64 + 64) * 128;     // ~34 KB
    const int SM2 = 1024 + 2 * (128 + 128) * 128;   // ~66 KB
    cudaFuncSetAttribute((const void*)mma_gemm<1, 64, 64>,
                         cudaFuncAttributeMaxDynamicSharedMemorySize, SM1);
    cudaFuncSetAttribute((const void*)mma_gemm<2, 128, 128>,
                         cudaFuncAttributeMaxDynamicSharedMemorySize, SM2);

    wnormT_kernel<<<(NP2 + 63) / 64, 64>>>(wh, gh, 0);
    wnormT_kernel<<<(NP1 + 63) / 64, 64>>>(wmh, gmh, 1);
    wnormX_kernel<<<(NP2 + 127) / 128, 128>>>(wx, gx, 0);
    wnormX_kernel<<<(NP1 + 127) / 128, 128>>>(wmx, gmx, 1);
    lengths_kernel<<<1, 256>>>(epi, lft, rgt);
    const int embN = TST * NB * 10 + TEPI * NB * 10;
    embed_kernel<<<(embN + 255) / 256, 256>>>(epi, tot, embed);
    init_kernel<<<(BB * NP1 + 255) / 256, 256>>>();

    for (int t = 0; t < TST; t++) {
        const int Mt = (t < TEPI) ? BB : NB;
        mma_gemm<1, 64, 64><<<dim3(NP1 / 64, Mt / 64), 256, SM1>>>(t, nullptr);
        mma_gemm<2, 128, 128><<<dim3(NP2 / 128, Mt / 128), 256, SM2>>>(t, bb);
        gates_kernel<<<(Mt * H + 255) / 256, 256>>>(t, Mt);
    }

    classifier_kernel<<<NB, 256>>>(
        (const float*)d_in[14], (const float*)d_in[15], (const float*)d_in[16], (const float*)d_in[17],
        (const float*)d_in[18], (const float*)d_in[19],
        (const float*)d_in[20], (const float*)d_in[21], (const float*)d_in[22], (const float*)d_in[23],
        (const float*)d_in[24], (const float*)d_in[25], out);
}